// round 1
// baseline (speedup 1.0000x reference)
#include <cuda_runtime.h>

// Problem constants (fixed by the reference)
constexpr int cN   = 50000;
constexpr int cE   = 400000;
constexpr int cR   = 3;
constexpr int cH   = 3;
constexpr int cIN  = 128;
constexpr int cHID = 64;
constexpr int cOUT = 64;
constexpr int cC   = 16;
constexpr int cB   = 8;
constexpr int cF2  = cH * cHID;   // 192
constexpr int cM   = cN * cH;     // 150000 rows for conv2

// ------------------------- device scratch (static, no alloc) -------------------------
__device__ float    g_ns[cR * cN];                      // src-degree norm per relation
__device__ float    g_nd[cR * cN];                      // dst-degree norm per relation
__device__ float    g_xW[cR * cN * cHID];               // x @ W1[r]  (un-normalized)
__device__ float    g_h1[cN * cHID];                    // conv1 out -> L2 normalized
__device__ float    g_f[(size_t)cR * cN * cF2];         // h1 @ Wg[r]
__device__ float    g_el[cR * cN * cH];
__device__ float    g_er[cR * cN * cH];
__device__ unsigned g_emax[cR * cN * cH];               // encoded float max
__device__ float    g_z[cR * cN * cH];                  // softmax denominators
__device__ float    g_e[(size_t)cR * cE * cH];          // edge logits -> exp values
__device__ float    g_gat[cN * cF2];                    // GAT accumulator [N,H,HID]
__device__ float    g_xW2[(size_t)cR * cM * cOUT];      // relu(gat) @ W2[r]
__device__ float    g_acc2[cM * cOUT];                  // conv2 accumulator [N,H,OUT]
__device__ float    g_pool[cB * cF2];
__device__ float    g_cnt[cB];

// ------------------------- helpers -------------------------
__device__ __forceinline__ void red4(float* p, float a, float b, float c, float d) {
    asm volatile("red.global.add.v4.f32 [%0], {%1,%2,%3,%4};"
                 :: "l"(p), "f"(a), "f"(b), "f"(c), "f"(d) : "memory");
}
// order-preserving float<->uint for atomicMax
__device__ __forceinline__ unsigned fenc(float f) {
    unsigned u = __float_as_uint(f);
    return (u & 0x80000000u) ? ~u : (u | 0x80000000u);
}
__device__ __forceinline__ float fdec(unsigned k) {
    return (k & 0x80000000u) ? __uint_as_float(k & 0x7fffffffu) : __uint_as_float(~k);
}
__device__ __forceinline__ float sigmoidf_(float v) { return 1.f / (1.f + expf(-v)); }

// ------------------------- init kernels -------------------------
__global__ void k_init0() {
    int i = blockIdx.x * blockDim.x + threadIdx.x;
    if (i < cR * cN)      { g_ns[i] = 0.f; g_nd[i] = 0.f; }
    if (i < cR * cN * cH) { g_z[i] = 0.f; g_emax[i] = 0u; }
    if (i < cB * cF2)     g_pool[i] = 0.f;
    if (i < cB)           g_cnt[i] = 0.f;
}

__global__ void k_init1(const float* __restrict__ b1, const float* __restrict__ bg,
                        const float* __restrict__ b2) {
    int i = blockIdx.x * blockDim.x + threadIdx.x;
    if (i >= cN * cF2) return;                        // == cM*cOUT
    int j = i % cF2;
    g_gat[i]  = bg[j] + bg[cF2 + j] + bg[2 * cF2 + j];
    int o = i % cOUT;
    g_acc2[i] = b2[o] + b2[cOUT + o] + b2[2 * cOUT + o];
    if (i < cN * cHID) {
        int jj = i % cHID;
        g_h1[i] = b1[jj] + b1[cHID + jj] + b1[2 * cHID + jj];
    }
}

// ------------------------- degrees -------------------------
__global__ void k_deg(const int* __restrict__ src, const int* __restrict__ dst) {
    int i = blockIdx.x * blockDim.x + threadIdx.x;
    if (i >= cR * cE) return;
    int r = i / cE;
    atomicAdd(&g_ns[r * cN + src[i]], 1.f);
    atomicAdd(&g_nd[r * cN + dst[i]], 1.f);
}
__global__ void k_norm() {
    int i = blockIdx.x * blockDim.x + threadIdx.x;
    if (i >= cR * cN) return;
    g_ns[i] = rsqrtf(fmaxf(g_ns[i], 1.f));
    g_nd[i] = rsqrtf(fmaxf(g_nd[i], 1.f));
}

// ------------------------- conv1 matmul: xW[r] = x @ W1[r] -------------------------
__global__ void k_mm1(const float* __restrict__ x, const float* __restrict__ W1) {
    __shared__ float sX[32 * 128];
    int r = blockIdx.y, n0 = blockIdx.x * 32, tid = threadIdx.x;   // 128 threads
    for (int t = tid; t < 32 * 128; t += 128) {
        int row = t >> 7;
        sX[t] = (n0 + row < cN) ? x[(size_t)(n0) * 128 + t] : 0.f;
    }
    __syncthreads();
    int j = tid & 63, half = tid >> 6;
    const float* Wp = W1 + r * cIN * cHID + j;
    float acc[16];
#pragma unroll
    for (int m = 0; m < 16; m++) acc[m] = 0.f;
    for (int k = 0; k < 128; k++) {
        float w = Wp[k * 64];
#pragma unroll
        for (int m = 0; m < 16; m++)
            acc[m] += sX[((half << 4) + m) * 128 + k] * w;
    }
#pragma unroll
    for (int m = 0; m < 16; m++) {
        int n = n0 + (half << 4) + m;
        if (n < cN) g_xW[(size_t)(r * cN + n) * 64 + j] = acc[m];
    }
}

// ------------------------- conv1 edge scatter (norms folded) -------------------------
__global__ void k_scat1(const int* __restrict__ src, const int* __restrict__ dst) {
    int i = blockIdx.x * blockDim.x + threadIdx.x;
    if (i >= cR * cE * 16) return;
    int lane = i & 15;
    int eid  = i >> 4;
    int r    = eid / cE;
    int s = src[eid], d = dst[eid];
    float sc = g_ns[r * cN + s] * g_nd[r * cN + d];
    const float4 v = *(const float4*)(g_xW + (size_t)(r * cN + s) * 64 + lane * 4);
    red4(g_h1 + (size_t)d * 64 + lane * 4, sc * v.x, sc * v.y, sc * v.z, sc * v.w);
}

// ------------------------- L2 row normalize -------------------------
__global__ void k_l2n() {
    int gtid = blockIdx.x * blockDim.x + threadIdx.x;
    int n = gtid >> 5, lane = gtid & 31;
    if (n >= cN) return;
    float a = g_h1[(size_t)n * 64 + lane];
    float b = g_h1[(size_t)n * 64 + 32 + lane];
    float ss = a * a + b * b;
#pragma unroll
    for (int off = 16; off; off >>= 1) ss += __shfl_xor_sync(0xffffffffu, ss, off);
    float inv = 1.f / fmaxf(sqrtf(ss), 1e-12f);
    g_h1[(size_t)n * 64 + lane]      = a * inv;
    g_h1[(size_t)n * 64 + 32 + lane] = b * inv;
}

// ------------------------- GAT feature matmul: f[r] = h1 @ Wg[r] -------------------------
__global__ void k_mmF(const float* __restrict__ Wg) {
    __shared__ float sH[16 * 64];
    int r = blockIdx.y, n0 = blockIdx.x * 16, tid = threadIdx.x;   // 192 threads
    for (int t = tid; t < 16 * 64; t += 192) {
        int row = t >> 6;
        sH[t] = (n0 + row < cN) ? g_h1[(size_t)n0 * 64 + t] : 0.f;
    }
    __syncthreads();
    const float* Wp = Wg + r * cHID * cF2 + tid;
    float acc[16];
#pragma unroll
    for (int m = 0; m < 16; m++) acc[m] = 0.f;
    for (int k = 0; k < 64; k++) {
        float w = Wp[k * cF2];
#pragma unroll
        for (int m = 0; m < 16; m++) acc[m] += sH[m * 64 + k] * w;
    }
#pragma unroll
    for (int m = 0; m < 16; m++) {
        int n = n0 + m;
        if (n < cN) g_f[((size_t)r * cN + n) * cF2 + tid] = acc[m];
    }
}

// ------------------------- attention logits el/er -------------------------
__global__ void k_eler(const float* __restrict__ al, const float* __restrict__ ar) {
    __shared__ float sF[32 * 200];          // stride 200 to break bank conflicts
    __shared__ float sA[2 * cF2];
    int r = blockIdx.y, n0 = blockIdx.x * 32, tid = threadIdx.x;   // 192 threads
    if (tid < cF2) { sA[tid] = al[r * cF2 + tid]; sA[cF2 + tid] = ar[r * cF2 + tid]; }
    for (int t = tid; t < 32 * 192; t += 192) {
        int row = t / 192, col = t - row * 192;
        sF[row * 200 + col] = (n0 + row < cN)
            ? g_f[((size_t)r * cN + n0 + row) * 192 + col] : 0.f;
    }
    __syncthreads();
    int node = tid / 6, slot = tid % 6, h = slot >> 1, isR = slot & 1;
    int n = n0 + node;
    if (n >= cN) return;
    const float* a  = sA + isR * cF2 + h * 64;
    const float* fr = sF + node * 200 + h * 64;
    float acc = 0.f;
#pragma unroll
    for (int k = 0; k < 64; k++) acc += fr[k] * a[k];
    float* outp = isR ? g_er : g_el;
    outp[(r * cN + n) * 3 + h] = acc;
}

// ------------------------- edge logits + segment max -------------------------
__global__ void k_e1(const int* __restrict__ src, const int* __restrict__ dst) {
    int i = blockIdx.x * blockDim.x + threadIdx.x;
    if (i >= cR * cE) return;
    int r = i / cE;
    int bs = (r * cN + src[i]) * 3, bd = (r * cN + dst[i]) * 3;
#pragma unroll
    for (int h = 0; h < 3; h++) {
        float v = g_el[bs + h] + g_er[bd + h];
        v = v > 0.f ? v : 0.2f * v;                 // leaky_relu(0.2)
        g_e[(size_t)i * 3 + h] = v;
        atomicMax(&g_emax[bd + h], fenc(v));
    }
}

// ------------------------- exp + segment sum -------------------------
__global__ void k_e2(const int* __restrict__ dst) {
    int i = blockIdx.x * blockDim.x + threadIdx.x;
    if (i >= cR * cE) return;
    int r = i / cE;
    int bd = (r * cN + dst[i]) * 3;
#pragma unroll
    for (int h = 0; h < 3; h++) {
        float v = g_e[(size_t)i * 3 + h];
        float m = fdec(g_emax[bd + h]);
        float ez = expf(v - m);
        g_e[(size_t)i * 3 + h] = ez;
        atomicAdd(&g_z[bd + h], ez);
    }
}

// ------------------------- GAT weighted scatter -------------------------
__global__ void k_e3(const int* __restrict__ src, const int* __restrict__ dst) {
    int i = blockIdx.x * blockDim.x + threadIdx.x;
    if (i >= cR * cE * cH * 16) return;
    int lane = i & 15;
    int t    = i >> 4;
    int h    = t % 3;
    int eid  = t / 3;
    int r    = eid / cE;
    int s = src[eid], d = dst[eid];
    float ez = g_e[(size_t)eid * 3 + h];
    float z  = g_z[(r * cN + d) * 3 + h];
    float alpha = ez / (z + 1e-9f);
    const float4 v = *(const float4*)(g_f + ((size_t)r * cN + s) * 192 + h * 64 + lane * 4);
    red4(g_gat + (size_t)(d * 3 + h) * 64 + lane * 4,
         alpha * v.x, alpha * v.y, alpha * v.z, alpha * v.w);
}

// ------------------------- conv2 matmul: relu(gat) @ W2[r], per head -------------------------
__global__ void k_mm2(const float* __restrict__ W2) {
    __shared__ float sX[32 * 64];
    int r = blockIdx.y, n0 = blockIdx.x * 32, tid = threadIdx.x;   // 128 threads, rows over cM
    for (int t = tid; t < 32 * 64; t += 128) {
        int row = t >> 6;
        float v = (n0 + row < cM) ? g_gat[(size_t)n0 * 64 + t] : 0.f;
        sX[t] = v > 0.f ? v : 0.f;                                  // relu
    }
    __syncthreads();
    int j = tid & 63, half = tid >> 6;
    const float* Wp = W2 + r * 64 * 64 + j;
    float acc[16];
#pragma unroll
    for (int m = 0; m < 16; m++) acc[m] = 0.f;
    for (int k = 0; k < 64; k++) {
        float w = Wp[k * 64];
#pragma unroll
        for (int m = 0; m < 16; m++)
            acc[m] += sX[((half << 4) + m) * 64 + k] * w;
    }
#pragma unroll
    for (int m = 0; m < 16; m++) {
        int n = n0 + (half << 4) + m;
        if (n < cM) g_xW2[((size_t)r * cM + n) * 64 + j] = acc[m];
    }
}

// ------------------------- conv2 edge scatter (norms folded) -------------------------
__global__ void k_scat2(const int* __restrict__ src, const int* __restrict__ dst) {
    int i = blockIdx.x * blockDim.x + threadIdx.x;
    if (i >= cR * cE * cH * 16) return;
    int lane = i & 15;
    int t    = i >> 4;
    int h    = t % 3;
    int eid  = t / 3;
    int r    = eid / cE;
    int s = src[eid], d = dst[eid];
    float sc = g_ns[r * cN + s] * g_nd[r * cN + d];
    const float4 v = *(const float4*)(g_xW2 + ((size_t)r * cM + s * 3 + h) * 64 + lane * 4);
    red4(g_acc2 + (size_t)(d * 3 + h) * 64 + lane * 4,
         sc * v.x, sc * v.y, sc * v.z, sc * v.w);
}

// ------------------------- node counts per graph -------------------------
__global__ void k_cnt(const int* __restrict__ gid) {
    int i = blockIdx.x * blockDim.x + threadIdx.x;
    if (i >= cN) return;
    int g = gid[i];
    unsigned m = __match_any_sync(__activemask(), g);
    int leader = __ffs(m) - 1;
    if ((threadIdx.x & 31) == leader)
        atomicAdd(&g_cnt[g], (float)__popc(m));
}

// ------------------------- sigmoid + graph pooling -------------------------
__global__ void k_pool(const int* __restrict__ gid) {
    int n0 = blockIdx.x * 256;
    int j  = threadIdx.x;                        // 192 threads
    int curg = -1;
    float a = 0.f;
    for (int m = 0; m < 256; m++) {
        int n = n0 + m;
        if (n >= cN) break;
        int g = gid[n];
        float v = sigmoidf_(g_acc2[(size_t)n * 192 + j]);
        if (g != curg) {
            if (curg >= 0) atomicAdd(&g_pool[curg * 192 + j], a);
            curg = g; a = 0.f;
        }
        a += v;
    }
    if (curg >= 0) atomicAdd(&g_pool[curg * 192 + j], a);
}

// ------------------------- final classifier + mean -------------------------
__global__ void k_final(const float* __restrict__ Wc, const float* __restrict__ bc,
                        float* __restrict__ out) {
    int t = threadIdx.x;                          // 384 threads
    int b = t / 48, rem = t % 48, h = rem / 16, c = rem & 15;
    float inv = 1.f / fmaxf(g_cnt[b], 1.f);
    const float* P = g_pool + (b * 3 + h) * 64;
    float dot = bc[c];
#pragma unroll
    for (int k = 0; k < 64; k++) dot += P[k] * inv * Wc[k * 16 + c];
    float sg = sigmoidf_(dot);
#pragma unroll
    for (int off = 8; off; off >>= 1) sg += __shfl_xor_sync(0xffffffffu, sg, off);
    if (c == 0) out[b * 3 + h] = sg * (1.f / 16.f);
}

// ------------------------- launcher -------------------------
extern "C" void kernel_launch(void* const* d_in, const int* in_sizes, int n_in,
                              void* d_out, int out_size) {
    const float* x   = (const float*)d_in[0];
    const int*   src = (const int*)  d_in[1];
    const int*   dst = (const int*)  d_in[2];
    const int*   gid = (const int*)  d_in[3];
    const float* W1  = (const float*)d_in[4];
    const float* b1  = (const float*)d_in[5];
    const float* Wg  = (const float*)d_in[6];
    const float* al  = (const float*)d_in[7];
    const float* ar  = (const float*)d_in[8];
    const float* bg  = (const float*)d_in[9];
    const float* W2  = (const float*)d_in[10];
    const float* b2  = (const float*)d_in[11];
    const float* Wc  = (const float*)d_in[12];
    const float* bc  = (const float*)d_in[13];
    float* out = (float*)d_out;

    k_init0<<<(cR * cN * cH + 255) / 256, 256>>>();
    k_init1<<<(cN * cF2 + 255) / 256, 256>>>(b1, bg, b2);
    k_deg<<<(cR * cE + 255) / 256, 256>>>(src, dst);
    k_norm<<<(cR * cN + 255) / 256, 256>>>();

    dim3 g1((cN + 31) / 32, cR);
    k_mm1<<<g1, 128>>>(x, W1);
    k_scat1<<<(cR * cE * 16 + 255) / 256, 256>>>(src, dst);
    k_l2n<<<(cN * 32 + 255) / 256, 256>>>();

    dim3 gF((cN + 15) / 16, cR);
    k_mmF<<<gF, 192>>>(Wg);
    dim3 gE((cN + 31) / 32, cR);
    k_eler<<<gE, 192>>>(al, ar);
    k_e1<<<(cR * cE + 255) / 256, 256>>>(src, dst);
    k_e2<<<(cR * cE + 255) / 256, 256>>>(dst);
    k_e3<<<(cR * cE * cH * 16 + 255) / 256, 256>>>(src, dst);

    dim3 g2((cM + 31) / 32, cR);
    k_mm2<<<g2, 128>>>(W2);
    k_scat2<<<(cR * cE * cH * 16 + 255) / 256, 256>>>(src, dst);

    k_cnt<<<(cN + 255) / 256, 256>>>(gid);
    k_pool<<<(cN + 255) / 256, 192>>>(gid);
    k_final<<<1, 384>>>(Wc, bc, out);
}

// round 2
// speedup vs baseline: 1.2141x; 1.2141x over previous
#include <cuda_runtime.h>

// Problem constants (fixed by the reference)
constexpr int cN   = 50000;
constexpr int cE   = 400000;
constexpr int cR   = 3;
constexpr int cH   = 3;
constexpr int cIN  = 128;
constexpr int cHID = 64;
constexpr int cOUT = 64;
constexpr int cC   = 16;
constexpr int cB   = 8;
constexpr int cF2  = cH * cHID;   // 192
constexpr int cM   = cN * cH;     // 150000 rows for conv2
constexpr int cRN  = cR * cN;     // 150000
constexpr int cRE  = cR * cE;     // 1.2M
constexpr int SCAN_NB = (cRN + 1023) / 1024;  // 147

// ------------------------- device scratch (static, no alloc) -------------------------
__device__ int      g_outdeg[cRN];
__device__ int      g_indeg[cRN];
__device__ float    g_ns[cRN];                          // src-degree norm per relation
__device__ float    g_nd[cRN];                          // dst-degree norm per relation
__device__ int      g_off[cRN + 1];                     // CSR offsets (flattened, per relation region)
__device__ int      g_cursor[cRN];
__device__ int      g_bsum[256];
__device__ int      g_esrc[cRE];                        // CSR: src node per slot
__device__ float    g_xW[cRN * cHID];                   // x @ W1[r]
__device__ float    g_h1[cN * cHID];                    // conv1 out, L2 normalized
__device__ float    g_f[(size_t)cRN * cF2];             // h1 @ Wg[r]
__device__ float    g_el[cRN * cH];
__device__ float    g_er[cRN * cH];
__device__ float    g_gat[cN * cF2];                    // relu(GAT out) [N,H,HID]
__device__ float    g_xW2[(size_t)cR * cM * cOUT];      // gat @ W2[r]
__device__ float    g_acc2[cM * cOUT];                  // sigmoid(conv2 out) [N,H,OUT]
__device__ float    g_pool[cB * cF2];
__device__ float    g_cnt[cB];

__device__ __forceinline__ float sigmoidf_(float v) { return 1.f / (1.f + __expf(-v)); }

// ------------------------- init -------------------------
__global__ void k_init0() {
    int i = blockIdx.x * blockDim.x + threadIdx.x;
    if (i < cRN) { g_outdeg[i] = 0; g_indeg[i] = 0; }
    if (i < cB * cF2) g_pool[i] = 0.f;
    if (i < cB)       g_cnt[i] = 0.f;
}

// ------------------------- degrees -------------------------
__global__ void k_deg(const int* __restrict__ src, const int* __restrict__ dst) {
    int i = blockIdx.x * blockDim.x + threadIdx.x;
    if (i >= cRE) return;
    int r = i / cE;
    atomicAdd(&g_outdeg[r * cN + src[i]], 1);
    atomicAdd(&g_indeg[r * cN + dst[i]], 1);
}
__global__ void k_norm() {
    int i = blockIdx.x * blockDim.x + threadIdx.x;
    if (i >= cRN) return;
    g_ns[i] = rsqrtf(fmaxf((float)g_outdeg[i], 1.f));
    g_nd[i] = rsqrtf(fmaxf((float)g_indeg[i], 1.f));
}

// ------------------------- exclusive scan of indeg -> offsets -------------------------
__global__ void k_scanA() {          // grid SCAN_NB, block 256, 1024 elems/block
    __shared__ int wsum[8];
    int tid = threadIdx.x, lane = tid & 31, wid = tid >> 5;
    int idx0 = blockIdx.x * 1024 + tid * 4;
    int v[4]; int s = 0;
#pragma unroll
    for (int k = 0; k < 4; k++) {
        int i = idx0 + k;
        int x = (i < cRN) ? g_indeg[i] : 0;
        v[k] = s; s += x;
    }
    int incl = s;
#pragma unroll
    for (int o = 1; o < 32; o <<= 1) {
        int t = __shfl_up_sync(0xffffffffu, incl, o);
        if (lane >= o) incl += t;
    }
    int excl = incl - s;
    if (lane == 31) wsum[wid] = incl;
    __syncthreads();
    if (tid == 0) {
        int a = 0;
#pragma unroll
        for (int w = 0; w < 8; w++) { int t = wsum[w]; wsum[w] = a; a += t; }
        g_bsum[blockIdx.x] = a;
    }
    __syncthreads();
    int base = wsum[wid] + excl;
#pragma unroll
    for (int k = 0; k < 4; k++) {
        int i = idx0 + k;
        if (i < cRN) g_off[i] = base + v[k];
    }
}
__global__ void k_scanB() {          // 1 block, 256 threads over SCAN_NB sums
    __shared__ int wsum[8];
    int tid = threadIdx.x, lane = tid & 31, wid = tid >> 5;
    int v = (tid < SCAN_NB) ? g_bsum[tid] : 0;
    int incl = v;
#pragma unroll
    for (int o = 1; o < 32; o <<= 1) {
        int t = __shfl_up_sync(0xffffffffu, incl, o);
        if (lane >= o) incl += t;
    }
    if (lane == 31) wsum[wid] = incl;
    __syncthreads();
    if (tid == 0) {
        int a = 0;
#pragma unroll
        for (int w = 0; w < 8; w++) { int t = wsum[w]; wsum[w] = a; a += t; }
    }
    __syncthreads();
    if (tid < SCAN_NB) g_bsum[tid] = wsum[wid] + incl - v;
}
__global__ void k_scanC() {
    int i = blockIdx.x * blockDim.x + threadIdx.x;
    if (i >= cRN) return;
    int o = g_off[i] + g_bsum[i >> 10];
    g_off[i] = o;
    g_cursor[i] = o;
    if (i == 0) g_off[cRN] = cRE;
}
__global__ void k_fill(const int* __restrict__ src, const int* __restrict__ dst) {
    int i = blockIdx.x * blockDim.x + threadIdx.x;
    if (i >= cRE) return;
    int r = i / cE;
    int pos = atomicAdd(&g_cursor[r * cN + dst[i]], 1);
    g_esrc[pos] = src[i];
}

// ------------------------- conv1 matmul: xW[r] = x @ W1[r] -------------------------
__global__ void k_mm1(const float* __restrict__ x, const float* __restrict__ W1) {
    __shared__ float sX[32 * 128];
    int r = blockIdx.y, n0 = blockIdx.x * 32, tid = threadIdx.x;   // 128 threads
    for (int t = tid; t < 32 * 128; t += 128) {
        int row = t >> 7;
        sX[t] = (n0 + row < cN) ? x[(size_t)n0 * 128 + t] : 0.f;
    }
    __syncthreads();
    int j = tid & 63, half = tid >> 6;
    const float* Wp = W1 + r * cIN * cHID + j;
    float acc[16];
#pragma unroll
    for (int m = 0; m < 16; m++) acc[m] = 0.f;
    for (int k = 0; k < 128; k++) {
        float w = Wp[k * 64];
#pragma unroll
        for (int m = 0; m < 16; m++)
            acc[m] += sX[((half << 4) + m) * 128 + k] * w;
    }
#pragma unroll
    for (int m = 0; m < 16; m++) {
        int n = n0 + (half << 4) + m;
        if (n < cN) g_xW[(size_t)(r * cN + n) * 64 + j] = acc[m];
    }
}

// ------------------------- conv1 gather + L2 normalize (fused) -------------------------
__global__ void k_gath1(const float* __restrict__ b1) {
    int gw = (blockIdx.x * blockDim.x + threadIdx.x) >> 5;
    int lane = threadIdx.x & 31;
    if (gw >= cN) return;
    int n = gw;
    float a0 = b1[lane]      + b1[64 + lane]  + b1[128 + lane];
    float a1 = b1[32 + lane] + b1[96 + lane]  + b1[160 + lane];
#pragma unroll
    for (int r = 0; r < 3; r++) {
        int idx = r * cN + n;
        float nd = g_nd[idx];
        int beg = g_off[idx], end = g_off[idx + 1];
        for (int j0 = beg; j0 < end; j0 += 32) {
            int myS = (j0 + lane < end) ? __ldg(&g_esrc[j0 + lane]) : 0;
            int cnt = min(32, end - j0);
            for (int t = 0; t < cnt; t++) {
                int s = __shfl_sync(0xffffffffu, myS, t);
                float sc = __ldg(&g_ns[r * cN + s]) * nd;
                const float* row = g_xW + (size_t)(r * cN + s) * 64;
                a0 += sc * __ldg(&row[lane]);
                a1 += sc * __ldg(&row[32 + lane]);
            }
        }
    }
    float ss = a0 * a0 + a1 * a1;
#pragma unroll
    for (int o = 16; o; o >>= 1) ss += __shfl_xor_sync(0xffffffffu, ss, o);
    float inv = 1.f / fmaxf(sqrtf(ss), 1e-12f);
    g_h1[(size_t)n * 64 + lane]      = a0 * inv;
    g_h1[(size_t)n * 64 + 32 + lane] = a1 * inv;
}

// ------------------------- GAT feature matmul: f[r] = h1 @ Wg[r] -------------------------
__global__ void k_mmF(const float* __restrict__ Wg) {
    __shared__ float sH[16 * 64];
    int r = blockIdx.y, n0 = blockIdx.x * 16, tid = threadIdx.x;   // 192 threads
    for (int t = tid; t < 16 * 64; t += 192) {
        int row = t >> 6;
        sH[t] = (n0 + row < cN) ? g_h1[(size_t)n0 * 64 + t] : 0.f;
    }
    __syncthreads();
    const float* Wp = Wg + r * cHID * cF2 + tid;
    float acc[16];
#pragma unroll
    for (int m = 0; m < 16; m++) acc[m] = 0.f;
    for (int k = 0; k < 64; k++) {
        float w = Wp[k * cF2];
#pragma unroll
        for (int m = 0; m < 16; m++) acc[m] += sH[m * 64 + k] * w;
    }
#pragma unroll
    for (int m = 0; m < 16; m++) {
        int n = n0 + m;
        if (n < cN) g_f[((size_t)r * cN + n) * cF2 + tid] = acc[m];
    }
}

// ------------------------- attention logits el/er -------------------------
__global__ void k_eler(const float* __restrict__ al, const float* __restrict__ ar) {
    __shared__ float sF[32 * 200];
    __shared__ float sA[2 * cF2];
    int r = blockIdx.y, n0 = blockIdx.x * 32, tid = threadIdx.x;   // 192 threads
    if (tid < cF2) { sA[tid] = al[r * cF2 + tid]; sA[cF2 + tid] = ar[r * cF2 + tid]; }
    for (int t = tid; t < 32 * 192; t += 192) {
        int row = t / 192, col = t - row * 192;
        sF[row * 200 + col] = (n0 + row < cN)
            ? g_f[((size_t)r * cN + n0 + row) * 192 + col] : 0.f;
    }
    __syncthreads();
    int node = tid / 6, slot = tid % 6, h = slot >> 1, isR = slot & 1;
    int n = n0 + node;
    if (n >= cN) return;
    const float* a  = sA + isR * cF2 + h * 64;
    const float* fr = sF + node * 200 + h * 64;
    float acc = 0.f;
#pragma unroll
    for (int k = 0; k < 64; k++) acc += fr[k] * a[k];
    float* outp = isR ? g_er : g_el;
    outp[(r * cN + n) * 3 + h] = acc;
}

// ------------------------- GAT gather: online softmax + weighted agg + relu -------------------------
__global__ void k_ggat(const float* __restrict__ bg) {
    int gw = (blockIdx.x * blockDim.x + threadIdx.x) >> 5;
    int lane = threadIdx.x & 31;
    if (gw >= cN) return;
    int n = gw;
    float acc[6];
#pragma unroll
    for (int k = 0; k < 6; k++) {
        int p = lane + 32 * k;
        acc[k] = bg[p] + bg[192 + p] + bg[384 + p];
    }
    const float NEG = -3.4e38f;
#pragma unroll
    for (int r = 0; r < 3; r++) {
        int idx = r * cN + n;
        float er0 = g_er[idx * 3 + 0], er1 = g_er[idx * 3 + 1], er2 = g_er[idx * 3 + 2];
        float m0 = NEG, m1 = NEG, m2 = NEG;
        float z0 = 0.f, z1 = 0.f, z2 = 0.f;
        float t0 = 0.f, t1 = 0.f, t2 = 0.f, t3 = 0.f, t4 = 0.f, t5 = 0.f;
        int beg = g_off[idx], end = g_off[idx + 1];
        for (int j0 = beg; j0 < end; j0 += 32) {
            int myS = (j0 + lane < end) ? __ldg(&g_esrc[j0 + lane]) : 0;
            int cnt = min(32, end - j0);
            for (int t = 0; t < cnt; t++) {
                int s = __shfl_sync(0xffffffffu, myS, t);
                size_t sb = (size_t)(r * cN + s);
                float e0 = __ldg(&g_el[sb * 3 + 0]) + er0;
                float e1 = __ldg(&g_el[sb * 3 + 1]) + er1;
                float e2 = __ldg(&g_el[sb * 3 + 2]) + er2;
                e0 = e0 > 0.f ? e0 : 0.2f * e0;
                e1 = e1 > 0.f ? e1 : 0.2f * e1;
                e2 = e2 > 0.f ? e2 : 0.2f * e2;
                const float* fr = g_f + sb * 192 + lane;
                float w0, w1, w2;
                if (e0 > m0) { float sc = __expf(m0 - e0); z0 *= sc; t0 *= sc; t1 *= sc; m0 = e0; w0 = 1.f; }
                else w0 = __expf(e0 - m0);
                if (e1 > m1) { float sc = __expf(m1 - e1); z1 *= sc; t2 *= sc; t3 *= sc; m1 = e1; w1 = 1.f; }
                else w1 = __expf(e1 - m1);
                if (e2 > m2) { float sc = __expf(m2 - e2); z2 *= sc; t4 *= sc; t5 *= sc; m2 = e2; w2 = 1.f; }
                else w2 = __expf(e2 - m2);
                z0 += w0; z1 += w1; z2 += w2;
                t0 += w0 * __ldg(&fr[0]);
                t1 += w0 * __ldg(&fr[32]);
                t2 += w1 * __ldg(&fr[64]);
                t3 += w1 * __ldg(&fr[96]);
                t4 += w2 * __ldg(&fr[128]);
                t5 += w2 * __ldg(&fr[160]);
            }
        }
        acc[0] += t0 / (z0 + 1e-9f);
        acc[1] += t1 / (z0 + 1e-9f);
        acc[2] += t2 / (z1 + 1e-9f);
        acc[3] += t3 / (z1 + 1e-9f);
        acc[4] += t4 / (z2 + 1e-9f);
        acc[5] += t5 / (z2 + 1e-9f);
    }
#pragma unroll
    for (int k = 0; k < 6; k++)
        g_gat[(size_t)n * 192 + lane + 32 * k] = fmaxf(acc[k], 0.f);   // fused relu
}

// ------------------------- conv2 matmul: gat @ W2[r], per head -------------------------
__global__ void k_mm2(const float* __restrict__ W2) {
    __shared__ float sX[32 * 64];
    int r = blockIdx.y, n0 = blockIdx.x * 32, tid = threadIdx.x;   // 128 threads, rows over cM
    for (int t = tid; t < 32 * 64; t += 128) {
        int row = t >> 6;
        sX[t] = (n0 + row < cM) ? g_gat[(size_t)n0 * 64 + t] : 0.f;
    }
    __syncthreads();
    int j = tid & 63, half = tid >> 6;
    const float* Wp = W2 + r * 64 * 64 + j;
    float acc[16];
#pragma unroll
    for (int m = 0; m < 16; m++) acc[m] = 0.f;
    for (int k = 0; k < 64; k++) {
        float w = Wp[k * 64];
#pragma unroll
        for (int m = 0; m < 16; m++)
            acc[m] += sX[((half << 4) + m) * 64 + k] * w;
    }
#pragma unroll
    for (int m = 0; m < 16; m++) {
        int n = n0 + (half << 4) + m;
        if (n < cM) g_xW2[((size_t)r * cM + n) * 64 + j] = acc[m];
    }
}

// ------------------------- conv2 gather + sigmoid (fused) -------------------------
__global__ void k_gath2(const float* __restrict__ b2) {
    int gw = (blockIdx.x * blockDim.x + threadIdx.x) >> 5;
    int lane = threadIdx.x & 31;
    if (gw >= cN) return;
    int n = gw;
    float acc[6];
#pragma unroll
    for (int k = 0; k < 6; k++) {
        int o = (lane + 32 * k) & 63;
        acc[k] = b2[o] + b2[64 + o] + b2[128 + o];
    }
#pragma unroll
    for (int r = 0; r < 3; r++) {
        int idx = r * cN + n;
        float nd = g_nd[idx];
        int beg = g_off[idx], end = g_off[idx + 1];
        for (int j0 = beg; j0 < end; j0 += 32) {
            int myS = (j0 + lane < end) ? __ldg(&g_esrc[j0 + lane]) : 0;
            int cnt = min(32, end - j0);
            for (int t = 0; t < cnt; t++) {
                int s = __shfl_sync(0xffffffffu, myS, t);
                float sc = __ldg(&g_ns[r * cN + s]) * nd;
                const float* row = g_xW2 + ((size_t)r * cM + (size_t)s * 3) * 64 + lane;
                acc[0] += sc * __ldg(&row[0]);
                acc[1] += sc * __ldg(&row[32]);
                acc[2] += sc * __ldg(&row[64]);
                acc[3] += sc * __ldg(&row[96]);
                acc[4] += sc * __ldg(&row[128]);
                acc[5] += sc * __ldg(&row[160]);
            }
        }
    }
#pragma unroll
    for (int k = 0; k < 6; k++)
        g_acc2[(size_t)n * 192 + lane + 32 * k] = sigmoidf_(acc[k]);   // fused sigmoid
}

// ------------------------- node counts per graph -------------------------
__global__ void k_cnt(const int* __restrict__ gid) {
    int i = blockIdx.x * blockDim.x + threadIdx.x;
    if (i >= cN) return;
    int g = gid[i];
    unsigned m = __match_any_sync(__activemask(), g);
    int leader = __ffs(m) - 1;
    if ((threadIdx.x & 31) == leader)
        atomicAdd(&g_cnt[g], (float)__popc(m));
}

// ------------------------- graph pooling (acc2 already sigmoid'd) -------------------------
__global__ void k_pool(const int* __restrict__ gid) {
    int n0 = blockIdx.x * 256;
    int j  = threadIdx.x;                        // 192 threads
    int curg = -1;
    float a = 0.f;
    for (int m = 0; m < 256; m++) {
        int n = n0 + m;
        if (n >= cN) break;
        int g = gid[n];
        float v = g_acc2[(size_t)n * 192 + j];
        if (g != curg) {
            if (curg >= 0) atomicAdd(&g_pool[curg * 192 + j], a);
            curg = g; a = 0.f;
        }
        a += v;
    }
    if (curg >= 0) atomicAdd(&g_pool[curg * 192 + j], a);
}

// ------------------------- final classifier + mean -------------------------
__global__ void k_final(const float* __restrict__ Wc, const float* __restrict__ bc,
                        float* __restrict__ out) {
    int t = threadIdx.x;                          // 384 threads
    int b = t / 48, rem = t % 48, h = rem / 16, c = rem & 15;
    float inv = 1.f / fmaxf(g_cnt[b], 1.f);
    const float* P = g_pool + (b * 3 + h) * 64;
    float dot = bc[c];
#pragma unroll
    for (int k = 0; k < 64; k++) dot += P[k] * inv * Wc[k * 16 + c];
    float sg = 1.f / (1.f + expf(-dot));
#pragma unroll
    for (int off = 8; off; off >>= 1) sg += __shfl_xor_sync(0xffffffffu, sg, off);
    if (c == 0) out[b * 3 + h] = sg * (1.f / 16.f);
}

// ------------------------- launcher -------------------------
extern "C" void kernel_launch(void* const* d_in, const int* in_sizes, int n_in,
                              void* d_out, int out_size) {
    const float* x   = (const float*)d_in[0];
    const int*   src = (const int*)  d_in[1];
    const int*   dst = (const int*)  d_in[2];
    const int*   gid = (const int*)  d_in[3];
    const float* W1  = (const float*)d_in[4];
    const float* b1  = (const float*)d_in[5];
    const float* Wg  = (const float*)d_in[6];
    const float* al  = (const float*)d_in[7];
    const float* ar  = (const float*)d_in[8];
    const float* bg  = (const float*)d_in[9];
    const float* W2  = (const float*)d_in[10];
    const float* b2  = (const float*)d_in[11];
    const float* Wc  = (const float*)d_in[12];
    const float* bc  = (const float*)d_in[13];
    float* out = (float*)d_out;

    // CSR build
    k_init0<<<(cRN + 255) / 256, 256>>>();
    k_deg<<<(cRE + 255) / 256, 256>>>(src, dst);
    k_norm<<<(cRN + 255) / 256, 256>>>();
    k_scanA<<<SCAN_NB, 256>>>();
    k_scanB<<<1, 256>>>();
    k_scanC<<<(cRN + 255) / 256, 256>>>();
    k_fill<<<(cRE + 255) / 256, 256>>>(src, dst);

    // layer 1
    dim3 g1((cN + 31) / 32, cR);
    k_mm1<<<g1, 128>>>(x, W1);
    k_gath1<<<(cN * 32 + 255) / 256, 256>>>(b1);

    // GAT
    dim3 gF((cN + 15) / 16, cR);
    k_mmF<<<gF, 192>>>(Wg);
    dim3 gE((cN + 31) / 32, cR);
    k_eler<<<gE, 192>>>(al, ar);
    k_ggat<<<(cN * 32 + 255) / 256, 256>>>(bg);

    // layer 2
    dim3 g2((cM + 31) / 32, cR);
    k_mm2<<<g2, 128>>>(W2);
    k_gath2<<<(cN * 32 + 255) / 256, 256>>>(b2);

    // pooling + classifier
    k_cnt<<<(cN + 255) / 256, 256>>>(gid);
    k_pool<<<(cN + 255) / 256, 192>>>(gid);
    k_final<<<1, 384>>>(Wc, bc, out);
}

// round 3
// speedup vs baseline: 1.2150x; 1.0007x over previous
#include <cuda_runtime.h>

// Problem constants (fixed by the reference)
constexpr int cN   = 50000;
constexpr int cE   = 400000;
constexpr int cR   = 3;
constexpr int cH   = 3;
constexpr int cIN  = 128;
constexpr int cHID = 64;
constexpr int cOUT = 64;
constexpr int cC   = 16;
constexpr int cB   = 8;
constexpr int cF2  = cH * cHID;   // 192
constexpr int cM   = cN * cH;     // 150000 rows for conv2
constexpr int cRN  = cR * cN;     // 150000
constexpr int cRE  = cR * cE;     // 1.2M
constexpr int SCAN_NB = (cRN + 1023) / 1024;  // 147

// ------------------------- device scratch (static, no alloc) -------------------------
__device__ int      g_outdeg[cRN];
__device__ int      g_indeg[cRN];
__device__ float    g_ns[cRN];                          // src-degree norm per relation
__device__ float    g_nd[cRN];                          // dst-degree norm per relation
__device__ int      g_off[cRN + 1];                     // CSR offsets (flattened, per relation region)
__device__ int      g_cursor[cRN];
__device__ int      g_bsum[256];
__device__ int      g_esrc[cRE];                        // CSR: src node per slot
__device__ float    g_xW[cRN * cHID];                   // x @ W1[r]
__device__ float    g_h1[cN * cHID];                    // conv1 out, L2 normalized
__device__ float    g_f[(size_t)cRN * cF2];             // h1 @ Wg[r]
__device__ float    g_el[cRN * cH];
__device__ float    g_er[cRN * cH];
__device__ float    g_gat[cN * cF2];                    // relu(GAT out) [N,H,HID]
__device__ float    g_xW2[(size_t)cR * cM * cOUT];      // gat @ W2[r]
__device__ float    g_acc2[cM * cOUT];                  // sigmoid(conv2 out) [N,H,OUT]
__device__ float    g_pool[cB * cF2];
__device__ float    g_cnt[cB];

__device__ __forceinline__ float sigmoidf_(float v) { return 1.f / (1.f + __expf(-v)); }

// ------------------------- init -------------------------
__global__ void k_init0() {
    int i = blockIdx.x * blockDim.x + threadIdx.x;
    if (i < cRN) { g_outdeg[i] = 0; g_indeg[i] = 0; }
    if (i < cB * cF2) g_pool[i] = 0.f;
    if (i < cB)       g_cnt[i] = 0.f;
}

// ------------------------- degrees -------------------------
__global__ void k_deg(const int* __restrict__ src, const int* __restrict__ dst) {
    int i = blockIdx.x * blockDim.x + threadIdx.x;
    if (i >= cRE) return;
    int r = i / cE;
    atomicAdd(&g_outdeg[r * cN + src[i]], 1);
    atomicAdd(&g_indeg[r * cN + dst[i]], 1);
}
__global__ void k_norm() {
    int i = blockIdx.x * blockDim.x + threadIdx.x;
    if (i >= cRN) return;
    g_ns[i] = rsqrtf(fmaxf((float)g_outdeg[i], 1.f));
    g_nd[i] = rsqrtf(fmaxf((float)g_indeg[i], 1.f));
}

// ------------------------- exclusive scan of indeg -> offsets -------------------------
__global__ void k_scanA() {          // grid SCAN_NB, block 256, 1024 elems/block
    __shared__ int wsum[8];
    int tid = threadIdx.x, lane = tid & 31, wid = tid >> 5;
    int idx0 = blockIdx.x * 1024 + tid * 4;
    int v[4]; int s = 0;
#pragma unroll
    for (int k = 0; k < 4; k++) {
        int i = idx0 + k;
        int x = (i < cRN) ? g_indeg[i] : 0;
        v[k] = s; s += x;
    }
    int incl = s;
#pragma unroll
    for (int o = 1; o < 32; o <<= 1) {
        int t = __shfl_up_sync(0xffffffffu, incl, o);
        if (lane >= o) incl += t;
    }
    int excl = incl - s;
    if (lane == 31) wsum[wid] = incl;
    __syncthreads();
    if (tid == 0) {
        int a = 0;
#pragma unroll
        for (int w = 0; w < 8; w++) { int t = wsum[w]; wsum[w] = a; a += t; }
        g_bsum[blockIdx.x] = a;
    }
    __syncthreads();
    int base = wsum[wid] + excl;
#pragma unroll
    for (int k = 0; k < 4; k++) {
        int i = idx0 + k;
        if (i < cRN) g_off[i] = base + v[k];
    }
}
__global__ void k_scanB() {          // 1 block, 256 threads over SCAN_NB sums
    __shared__ int wsum[8];
    int tid = threadIdx.x, lane = tid & 31, wid = tid >> 5;
    int v = (tid < SCAN_NB) ? g_bsum[tid] : 0;
    int incl = v;
#pragma unroll
    for (int o = 1; o < 32; o <<= 1) {
        int t = __shfl_up_sync(0xffffffffu, incl, o);
        if (lane >= o) incl += t;
    }
    if (lane == 31) wsum[wid] = incl;
    __syncthreads();
    if (tid == 0) {
        int a = 0;
#pragma unroll
        for (int w = 0; w < 8; w++) { int t = wsum[w]; wsum[w] = a; a += t; }
    }
    __syncthreads();
    if (tid < SCAN_NB) g_bsum[tid] = wsum[wid] + incl - v;
}
__global__ void k_scanC() {
    int i = blockIdx.x * blockDim.x + threadIdx.x;
    if (i >= cRN) return;
    int o = g_off[i] + g_bsum[i >> 10];
    g_off[i] = o;
    g_cursor[i] = o;
    if (i == 0) g_off[cRN] = cRE;
}
__global__ void k_fill(const int* __restrict__ src, const int* __restrict__ dst) {
    int i = blockIdx.x * blockDim.x + threadIdx.x;
    if (i >= cRE) return;
    int r = i / cE;
    int pos = atomicAdd(&g_cursor[r * cN + dst[i]], 1);
    g_esrc[pos] = src[i];
}

// ------------------------- conv1 matmul: xW[r] = x @ W1[r] -------------------------
__global__ void k_mm1(const float* __restrict__ x, const float* __restrict__ W1) {
    __shared__ float sX[32 * 128];
    int r = blockIdx.y, n0 = blockIdx.x * 32, tid = threadIdx.x;   // 128 threads
    for (int t = tid; t < 32 * 128; t += 128) {
        int row = t >> 7;
        sX[t] = (n0 + row < cN) ? x[(size_t)n0 * 128 + t] : 0.f;
    }
    __syncthreads();
    int j = tid & 63, half = tid >> 6;
    const float* Wp = W1 + r * cIN * cHID + j;
    float acc[16];
#pragma unroll
    for (int m = 0; m < 16; m++) acc[m] = 0.f;
    for (int k = 0; k < 128; k++) {
        float w = Wp[k * 64];
#pragma unroll
        for (int m = 0; m < 16; m++)
            acc[m] += sX[((half << 4) + m) * 128 + k] * w;
    }
#pragma unroll
    for (int m = 0; m < 16; m++) {
        int n = n0 + (half << 4) + m;
        if (n < cN) g_xW[(size_t)(r * cN + n) * 64 + j] = acc[m];
    }
}

// ------------------------- conv1 gather + L2 normalize (fused) -------------------------
__global__ void k_gath1(const float* __restrict__ b1) {
    int gw = (blockIdx.x * blockDim.x + threadIdx.x) >> 5;
    int lane = threadIdx.x & 31;
    if (gw >= cN) return;
    int n = gw;
    float a0 = b1[lane]      + b1[64 + lane]  + b1[128 + lane];
    float a1 = b1[32 + lane] + b1[96 + lane]  + b1[160 + lane];
#pragma unroll
    for (int r = 0; r < 3; r++) {
        int idx = r * cN + n;
        float nd = g_nd[idx];
        int beg = g_off[idx], end = g_off[idx + 1];
        for (int j0 = beg; j0 < end; j0 += 32) {
            int myS = (j0 + lane < end) ? __ldg(&g_esrc[j0 + lane]) : 0;
            int cnt = min(32, end - j0);
            for (int t = 0; t < cnt; t++) {
                int s = __shfl_sync(0xffffffffu, myS, t);
                float sc = __ldg(&g_ns[r * cN + s]) * nd;
                const float* row = g_xW + (size_t)(r * cN + s) * 64;
                a0 += sc * __ldg(&row[lane]);
                a1 += sc * __ldg(&row[32 + lane]);
            }
        }
    }
    float ss = a0 * a0 + a1 * a1;
#pragma unroll
    for (int o = 16; o; o >>= 1) ss += __shfl_xor_sync(0xffffffffu, ss, o);
    float inv = 1.f / fmaxf(sqrtf(ss), 1e-12f);
    g_h1[(size_t)n * 64 + lane]      = a0 * inv;
    g_h1[(size_t)n * 64 + 32 + lane] = a1 * inv;
}

// ------------------------- GAT feature matmul: f[r] = h1 @ Wg[r] -------------------------
__global__ void k_mmF(const float* __restrict__ Wg) {
    __shared__ float sH[16 * 64];
    int r = blockIdx.y, n0 = blockIdx.x * 16, tid = threadIdx.x;   // 192 threads
    for (int t = tid; t < 16 * 64; t += 192) {
        int row = t >> 6;
        sH[t] = (n0 + row < cN) ? g_h1[(size_t)n0 * 64 + t] : 0.f;
    }
    __syncthreads();
    const float* Wp = Wg + r * cHID * cF2 + tid;
    float acc[16];
#pragma unroll
    for (int m = 0; m < 16; m++) acc[m] = 0.f;
    for (int k = 0; k < 64; k++) {
        float w = Wp[k * cF2];
#pragma unroll
        for (int m = 0; m < 16; m++) acc[m] += sH[m * 64 + k] * w;
    }
#pragma unroll
    for (int m = 0; m < 16; m++) {
        int n = n0 + m;
        if (n < cN) g_f[((size_t)r * cN + n) * cF2 + tid] = acc[m];
    }
}

// ------------------------- attention logits el/er -------------------------
__global__ void k_eler(const float* __restrict__ al, const float* __restrict__ ar) {
    __shared__ float sF[32 * 200];
    __shared__ float sA[2 * cF2];
    int r = blockIdx.y, n0 = blockIdx.x * 32, tid = threadIdx.x;   // 192 threads
    if (tid < cF2) { sA[tid] = al[r * cF2 + tid]; sA[cF2 + tid] = ar[r * cF2 + tid]; }
    for (int t = tid; t < 32 * 192; t += 192) {
        int row = t / 192, col = t - row * 192;
        sF[row * 200 + col] = (n0 + row < cN)
            ? g_f[((size_t)r * cN + n0 + row) * 192 + col] : 0.f;
    }
    __syncthreads();
    int node = tid / 6, slot = tid % 6, h = slot >> 1, isR = slot & 1;
    int n = n0 + node;
    if (n >= cN) return;
    const float* a  = sA + isR * cF2 + h * 64;
    const float* fr = sF + node * 200 + h * 64;
    float acc = 0.f;
#pragma unroll
    for (int k = 0; k < 64; k++) acc += fr[k] * a[k];
    float* outp = isR ? g_er : g_el;
    outp[(r * cN + n) * 3 + h] = acc;
}

// ------------------------- GAT gather: online softmax + weighted agg + relu -------------------------
__global__ void k_ggat(const float* __restrict__ bg) {
    int gw = (blockIdx.x * blockDim.x + threadIdx.x) >> 5;
    int lane = threadIdx.x & 31;
    if (gw >= cN) return;
    int n = gw;
    float acc[6];
#pragma unroll
    for (int k = 0; k < 6; k++) {
        int p = lane + 32 * k;
        acc[k] = bg[p] + bg[192 + p] + bg[384 + p];
    }
    const float NEG = -3.4e38f;
#pragma unroll
    for (int r = 0; r < 3; r++) {
        int idx = r * cN + n;
        float er0 = g_er[idx * 3 + 0], er1 = g_er[idx * 3 + 1], er2 = g_er[idx * 3 + 2];
        float m0 = NEG, m1 = NEG, m2 = NEG;
        float z0 = 0.f, z1 = 0.f, z2 = 0.f;
        float t0 = 0.f, t1 = 0.f, t2 = 0.f, t3 = 0.f, t4 = 0.f, t5 = 0.f;
        int beg = g_off[idx], end = g_off[idx + 1];
        for (int j0 = beg; j0 < end; j0 += 32) {
            int myS = (j0 + lane < end) ? __ldg(&g_esrc[j0 + lane]) : 0;
            int cnt = min(32, end - j0);
            for (int t = 0; t < cnt; t++) {
                int s = __shfl_sync(0xffffffffu, myS, t);
                size_t sb = (size_t)(r * cN + s);
                float e0 = __ldg(&g_el[sb * 3 + 0]) + er0;
                float e1 = __ldg(&g_el[sb * 3 + 1]) + er1;
                float e2 = __ldg(&g_el[sb * 3 + 2]) + er2;
                e0 = e0 > 0.f ? e0 : 0.2f * e0;
                e1 = e1 > 0.f ? e1 : 0.2f * e1;
                e2 = e2 > 0.f ? e2 : 0.2f * e2;
                const float* fr = g_f + sb * 192 + lane;
                float w0, w1, w2;
                if (e0 > m0) { float sc = __expf(m0 - e0); z0 *= sc; t0 *= sc; t1 *= sc; m0 = e0; w0 = 1.f; }
                else w0 = __expf(e0 - m0);
                if (e1 > m1) { float sc = __expf(m1 - e1); z1 *= sc; t2 *= sc; t3 *= sc; m1 = e1; w1 = 1.f; }
                else w1 = __expf(e1 - m1);
                if (e2 > m2) { float sc = __expf(m2 - e2); z2 *= sc; t4 *= sc; t5 *= sc; m2 = e2; w2 = 1.f; }
                else w2 = __expf(e2 - m2);
                z0 += w0; z1 += w1; z2 += w2;
                t0 += w0 * __ldg(&fr[0]);
                t1 += w0 * __ldg(&fr[32]);
                t2 += w1 * __ldg(&fr[64]);
                t3 += w1 * __ldg(&fr[96]);
                t4 += w2 * __ldg(&fr[128]);
                t5 += w2 * __ldg(&fr[160]);
            }
        }
        acc[0] += t0 / (z0 + 1e-9f);
        acc[1] += t1 / (z0 + 1e-9f);
        acc[2] += t2 / (z1 + 1e-9f);
        acc[3] += t3 / (z1 + 1e-9f);
        acc[4] += t4 / (z2 + 1e-9f);
        acc[5] += t5 / (z2 + 1e-9f);
    }
#pragma unroll
    for (int k = 0; k < 6; k++)
        g_gat[(size_t)n * 192 + lane + 32 * k] = fmaxf(acc[k], 0.f);   // fused relu
}

// ------------------------- conv2 matmul: gat @ W2[r], per head -------------------------
__global__ void k_mm2(const float* __restrict__ W2) {
    __shared__ float sX[32 * 64];
    int r = blockIdx.y, n0 = blockIdx.x * 32, tid = threadIdx.x;   // 128 threads, rows over cM
    for (int t = tid; t < 32 * 64; t += 128) {
        int row = t >> 6;
        sX[t] = (n0 + row < cM) ? g_gat[(size_t)n0 * 64 + t] : 0.f;
    }
    __syncthreads();
    int j = tid & 63, half = tid >> 6;
    const float* Wp = W2 + r * 64 * 64 + j;
    float acc[16];
#pragma unroll
    for (int m = 0; m < 16; m++) acc[m] = 0.f;
    for (int k = 0; k < 64; k++) {
        float w = Wp[k * 64];
#pragma unroll
        for (int m = 0; m < 16; m++)
            acc[m] += sX[((half << 4) + m) * 64 + k] * w;
    }
#pragma unroll
    for (int m = 0; m < 16; m++) {
        int n = n0 + (half << 4) + m;
        if (n < cM) g_xW2[((size_t)r * cM + n) * 64 + j] = acc[m];
    }
}

// ------------------------- conv2 gather + sigmoid (fused) -------------------------
__global__ void k_gath2(const float* __restrict__ b2) {
    int gw = (blockIdx.x * blockDim.x + threadIdx.x) >> 5;
    int lane = threadIdx.x & 31;
    if (gw >= cN) return;
    int n = gw;
    float acc[6];
#pragma unroll
    for (int k = 0; k < 6; k++) {
        int o = (lane + 32 * k) & 63;
        acc[k] = b2[o] + b2[64 + o] + b2[128 + o];
    }
#pragma unroll
    for (int r = 0; r < 3; r++) {
        int idx = r * cN + n;
        float nd = g_nd[idx];
        int beg = g_off[idx], end = g_off[idx + 1];
        for (int j0 = beg; j0 < end; j0 += 32) {
            int myS = (j0 + lane < end) ? __ldg(&g_esrc[j0 + lane]) : 0;
            int cnt = min(32, end - j0);
            for (int t = 0; t < cnt; t++) {
                int s = __shfl_sync(0xffffffffu, myS, t);
                float sc = __ldg(&g_ns[r * cN + s]) * nd;
                const float* row = g_xW2 + ((size_t)r * cM + (size_t)s * 3) * 64 + lane;
                acc[0] += sc * __ldg(&row[0]);
                acc[1] += sc * __ldg(&row[32]);
                acc[2] += sc * __ldg(&row[64]);
                acc[3] += sc * __ldg(&row[96]);
                acc[4] += sc * __ldg(&row[128]);
                acc[5] += sc * __ldg(&row[160]);
            }
        }
    }
#pragma unroll
    for (int k = 0; k < 6; k++)
        g_acc2[(size_t)n * 192 + lane + 32 * k] = sigmoidf_(acc[k]);   // fused sigmoid
}

// ------------------------- node counts per graph -------------------------
__global__ void k_cnt(const int* __restrict__ gid) {
    int i = blockIdx.x * blockDim.x + threadIdx.x;
    if (i >= cN) return;
    int g = gid[i];
    unsigned m = __match_any_sync(__activemask(), g);
    int leader = __ffs(m) - 1;
    if ((threadIdx.x & 31) == leader)
        atomicAdd(&g_cnt[g], (float)__popc(m));
}

// ------------------------- graph pooling (acc2 already sigmoid'd) -------------------------
__global__ void k_pool(const int* __restrict__ gid) {
    int n0 = blockIdx.x * 256;
    int j  = threadIdx.x;                        // 192 threads
    int curg = -1;
    float a = 0.f;
    for (int m = 0; m < 256; m++) {
        int n = n0 + m;
        if (n >= cN) break;
        int g = gid[n];
        float v = g_acc2[(size_t)n * 192 + j];
        if (g != curg) {
            if (curg >= 0) atomicAdd(&g_pool[curg * 192 + j], a);
            curg = g; a = 0.f;
        }
        a += v;
    }
    if (curg >= 0) atomicAdd(&g_pool[curg * 192 + j], a);
}

// ------------------------- final classifier + mean -------------------------
__global__ void k_final(const float* __restrict__ Wc, const float* __restrict__ bc,
                        float* __restrict__ out) {
    int t = threadIdx.x;                          // 384 threads
    int b = t / 48, rem = t % 48, h = rem / 16, c = rem & 15;
    float inv = 1.f / fmaxf(g_cnt[b], 1.f);
    const float* P = g_pool + (b * 3 + h) * 64;
    float dot = bc[c];
#pragma unroll
    for (int k = 0; k < 64; k++) dot += P[k] * inv * Wc[k * 16 + c];
    float sg = 1.f / (1.f + expf(-dot));
#pragma unroll
    for (int off = 8; off; off >>= 1) sg += __shfl_xor_sync(0xffffffffu, sg, off);
    if (c == 0) out[b * 3 + h] = sg * (1.f / 16.f);
}

// ------------------------- launcher -------------------------
extern "C" void kernel_launch(void* const* d_in, const int* in_sizes, int n_in,
                              void* d_out, int out_size) {
    const float* x   = (const float*)d_in[0];
    const int*   src = (const int*)  d_in[1];
    const int*   dst = (const int*)  d_in[2];
    const int*   gid = (const int*)  d_in[3];
    const float* W1  = (const float*)d_in[4];
    const float* b1  = (const float*)d_in[5];
    const float* Wg  = (const float*)d_in[6];
    const float* al  = (const float*)d_in[7];
    const float* ar  = (const float*)d_in[8];
    const float* bg  = (const float*)d_in[9];
    const float* W2  = (const float*)d_in[10];
    const float* b2  = (const float*)d_in[11];
    const float* Wc  = (const float*)d_in[12];
    const float* bc  = (const float*)d_in[13];
    float* out = (float*)d_out;

    // CSR build
    k_init0<<<(cRN + 255) / 256, 256>>>();
    k_deg<<<(cRE + 255) / 256, 256>>>(src, dst);
    k_norm<<<(cRN + 255) / 256, 256>>>();
    k_scanA<<<SCAN_NB, 256>>>();
    k_scanB<<<1, 256>>>();
    k_scanC<<<(cRN + 255) / 256, 256>>>();
    k_fill<<<(cRE + 255) / 256, 256>>>(src, dst);

    // layer 1
    dim3 g1((cN + 31) / 32, cR);
    k_mm1<<<g1, 128>>>(x, W1);
    k_gath1<<<(cN * 32 + 255) / 256, 256>>>(b1);

    // GAT
    dim3 gF((cN + 15) / 16, cR);
    k_mmF<<<gF, 192>>>(Wg);
    dim3 gE((cN + 31) / 32, cR);
    k_eler<<<gE, 192>>>(al, ar);
    k_ggat<<<(cN * 32 + 255) / 256, 256>>>(bg);

    // layer 2
    dim3 g2((cM + 31) / 32, cR);
    k_mm2<<<g2, 128>>>(W2);
    k_gath2<<<(cN * 32 + 255) / 256, 256>>>(b2);

    // pooling + classifier
    k_cnt<<<(cN + 255) / 256, 256>>>(gid);
    k_pool<<<(cN + 255) / 256, 192>>>(gid);
    k_final<<<1, 384>>>(Wc, bc, out);
}

// round 4
// speedup vs baseline: 1.5248x; 1.2550x over previous
#include <cuda_runtime.h>

// Problem constants (fixed by the reference)
constexpr int cN   = 50000;
constexpr int cE   = 400000;
constexpr int cR   = 3;
constexpr int cH   = 3;
constexpr int cIN  = 128;
constexpr int cHID = 64;
constexpr int cOUT = 64;
constexpr int cC   = 16;
constexpr int cB   = 8;
constexpr int cF2  = cH * cHID;   // 192
constexpr int cM   = cN * cH;     // 150000 rows for conv2
constexpr int cRN  = cR * cN;     // 150000
constexpr int cRE  = cR * cE;     // 1.2M
constexpr int SCAN_NB = (cRN + 1023) / 1024;  // 147

// ------------------------- device scratch (static, no alloc) -------------------------
__device__ int      g_outdeg[cRN];
__device__ int      g_indeg[cRN];
__device__ float    g_ns[cRN];
__device__ float    g_nd[cRN];
__device__ int      g_off[cRN + 1];
__device__ int      g_cursor[cRN];
__device__ int      g_bsum[256];
__device__ int      g_esrc[cRE];
__device__ float    g_xW[cRN * cHID];
__device__ float    g_h1[cN * cHID];
__device__ float    g_f[(size_t)cRN * cF2];
__device__ float    g_el4[cRN * 4];                 // padded: [idx*4 + h], h<3
__device__ float    g_er4[cRN * 4];
__device__ float    g_gat[cN * cF2];
__device__ float    g_xW2[(size_t)cR * cM * cOUT];
__device__ float    g_acc2[cM * cOUT];
__device__ float    g_pool[cB * cF2];
__device__ float    g_cnt[cB];

__device__ __forceinline__ float sigmoidf_(float v) { return 1.f / (1.f + __expf(-v)); }

// ------------------------- init -------------------------
__global__ void k_init0() {
    int i = blockIdx.x * blockDim.x + threadIdx.x;
    if (i < cRN) { g_outdeg[i] = 0; g_indeg[i] = 0; }
    if (i < cB * cF2) g_pool[i] = 0.f;
    if (i < cB)       g_cnt[i] = 0.f;
}

// ------------------------- degrees -------------------------
__global__ void k_deg(const int* __restrict__ src, const int* __restrict__ dst) {
    int i = blockIdx.x * blockDim.x + threadIdx.x;
    if (i >= cRE) return;
    int r = i / cE;
    atomicAdd(&g_outdeg[r * cN + src[i]], 1);
    atomicAdd(&g_indeg[r * cN + dst[i]], 1);
}
__global__ void k_norm() {
    int i = blockIdx.x * blockDim.x + threadIdx.x;
    if (i >= cRN) return;
    g_ns[i] = rsqrtf(fmaxf((float)g_outdeg[i], 1.f));
    g_nd[i] = rsqrtf(fmaxf((float)g_indeg[i], 1.f));
}

// ------------------------- exclusive scan of indeg -> offsets -------------------------
__global__ void k_scanA() {
    __shared__ int wsum[8];
    int tid = threadIdx.x, lane = tid & 31, wid = tid >> 5;
    int idx0 = blockIdx.x * 1024 + tid * 4;
    int v[4]; int s = 0;
#pragma unroll
    for (int k = 0; k < 4; k++) {
        int i = idx0 + k;
        int x = (i < cRN) ? g_indeg[i] : 0;
        v[k] = s; s += x;
    }
    int incl = s;
#pragma unroll
    for (int o = 1; o < 32; o <<= 1) {
        int t = __shfl_up_sync(0xffffffffu, incl, o);
        if (lane >= o) incl += t;
    }
    int excl = incl - s;
    if (lane == 31) wsum[wid] = incl;
    __syncthreads();
    if (tid == 0) {
        int a = 0;
#pragma unroll
        for (int w = 0; w < 8; w++) { int t = wsum[w]; wsum[w] = a; a += t; }
        g_bsum[blockIdx.x] = a;
    }
    __syncthreads();
    int base = wsum[wid] + excl;
#pragma unroll
    for (int k = 0; k < 4; k++) {
        int i = idx0 + k;
        if (i < cRN) g_off[i] = base + v[k];
    }
}
__global__ void k_scanB() {
    __shared__ int wsum[8];
    int tid = threadIdx.x, lane = tid & 31, wid = tid >> 5;
    int v = (tid < SCAN_NB) ? g_bsum[tid] : 0;
    int incl = v;
#pragma unroll
    for (int o = 1; o < 32; o <<= 1) {
        int t = __shfl_up_sync(0xffffffffu, incl, o);
        if (lane >= o) incl += t;
    }
    if (lane == 31) wsum[wid] = incl;
    __syncthreads();
    if (tid == 0) {
        int a = 0;
#pragma unroll
        for (int w = 0; w < 8; w++) { int t = wsum[w]; wsum[w] = a; a += t; }
    }
    __syncthreads();
    if (tid < SCAN_NB) g_bsum[tid] = wsum[wid] + incl - v;
}
__global__ void k_scanC() {
    int i = blockIdx.x * blockDim.x + threadIdx.x;
    if (i >= cRN) return;
    int o = g_off[i] + g_bsum[i >> 10];
    g_off[i] = o;
    g_cursor[i] = o;
    if (i == 0) g_off[cRN] = cRE;
}
__global__ void k_fill(const int* __restrict__ src, const int* __restrict__ dst) {
    int i = blockIdx.x * blockDim.x + threadIdx.x;
    if (i >= cRE) return;
    int r = i / cE;
    int pos = atomicAdd(&g_cursor[r * cN + dst[i]], 1);
    g_esrc[pos] = src[i];
}

// ------------------------- conv1 matmul: xW[r] = x @ W1[r] -------------------------
__global__ void k_mm1(const float* __restrict__ x, const float* __restrict__ W1) {
    __shared__ float sX[32 * 128];
    int r = blockIdx.y, n0 = blockIdx.x * 32, tid = threadIdx.x;   // 128 threads
    for (int t = tid; t < 32 * 128; t += 128) {
        int row = t >> 7;
        sX[t] = (n0 + row < cN) ? x[(size_t)n0 * 128 + t] : 0.f;
    }
    __syncthreads();
    int j = tid & 63, half = tid >> 6;
    const float* Wp = W1 + r * cIN * cHID + j;
    float acc[16];
#pragma unroll
    for (int m = 0; m < 16; m++) acc[m] = 0.f;
    for (int k = 0; k < 128; k++) {
        float w = Wp[k * 64];
#pragma unroll
        for (int m = 0; m < 16; m++)
            acc[m] += sX[((half << 4) + m) * 128 + k] * w;
    }
#pragma unroll
    for (int m = 0; m < 16; m++) {
        int n = n0 + (half << 4) + m;
        if (n < cN) g_xW[(size_t)(r * cN + n) * 64 + j] = acc[m];
    }
}

// ------------------------- conv1 gather + L2 normalize (fused) -------------------------
__global__ void __launch_bounds__(256) k_gath1(const float* __restrict__ b1) {
    int gw = blockIdx.x * 8 + (threadIdx.x >> 5);
    int lane = threadIdx.x & 31;
    if (gw >= cN) return;
    int n = gw;
    int p = lane * 2;
    float2 a;
    a.x = b1[p]     + b1[64 + p]     + b1[128 + p];
    a.y = b1[p + 1] + b1[64 + p + 1] + b1[128 + p + 1];
#define G1_BODY(J) { \
    int s_ = __ldg(&g_esrc[J]); \
    float sc_ = __ldg(&g_ns[r * cN + s_]) * nd; \
    float2 v_ = __ldg((const float2*)(g_xW + (size_t)(r * cN + s_) * 64) + lane); \
    a.x += sc_ * v_.x; a.y += sc_ * v_.y; }
#pragma unroll
    for (int r = 0; r < 3; r++) {
        int idx = r * cN + n;
        float nd = g_nd[idx];
        int beg = g_off[idx], end = g_off[idx + 1];
        int j = beg;
        for (; j + 4 <= end; j += 4) { G1_BODY(j) G1_BODY(j + 1) G1_BODY(j + 2) G1_BODY(j + 3) }
        for (; j < end; ++j) { G1_BODY(j) }
    }
#undef G1_BODY
    float ss = a.x * a.x + a.y * a.y;
#pragma unroll
    for (int o = 16; o; o >>= 1) ss += __shfl_xor_sync(0xffffffffu, ss, o);
    float inv = 1.f / fmaxf(sqrtf(ss), 1e-12f);
    float2* outp = (float2*)(g_h1 + (size_t)n * 64) + lane;
    outp->x = a.x * inv; outp->y = a.y * inv;
}

// ------------------------- GAT feature matmul: f[r] = h1 @ Wg[r] -------------------------
__global__ void k_mmF(const float* __restrict__ Wg) {
    __shared__ float sH[16 * 64];
    int r = blockIdx.y, n0 = blockIdx.x * 16, tid = threadIdx.x;   // 192 threads
    for (int t = tid; t < 16 * 64; t += 192) {
        int row = t >> 6;
        sH[t] = (n0 + row < cN) ? g_h1[(size_t)n0 * 64 + t] : 0.f;
    }
    __syncthreads();
    const float* Wp = Wg + r * cHID * cF2 + tid;
    float acc[16];
#pragma unroll
    for (int m = 0; m < 16; m++) acc[m] = 0.f;
    for (int k = 0; k < 64; k++) {
        float w = Wp[k * cF2];
#pragma unroll
        for (int m = 0; m < 16; m++) acc[m] += sH[m * 64 + k] * w;
    }
#pragma unroll
    for (int m = 0; m < 16; m++) {
        int n = n0 + m;
        if (n < cN) g_f[((size_t)r * cN + n) * cF2 + tid] = acc[m];
    }
}

// ------------------------- attention logits el/er (padded to 4) -------------------------
__global__ void k_eler(const float* __restrict__ al, const float* __restrict__ ar) {
    __shared__ float sF[32 * 200];
    __shared__ float sA[2 * cF2];
    int r = blockIdx.y, n0 = blockIdx.x * 32, tid = threadIdx.x;   // 192 threads
    if (tid < cF2) { sA[tid] = al[r * cF2 + tid]; sA[cF2 + tid] = ar[r * cF2 + tid]; }
    for (int t = tid; t < 32 * 192; t += 192) {
        int row = t / 192, col = t - row * 192;
        sF[row * 200 + col] = (n0 + row < cN)
            ? g_f[((size_t)r * cN + n0 + row) * 192 + col] : 0.f;
    }
    __syncthreads();
    int node = tid / 6, slot = tid % 6, h = slot >> 1, isR = slot & 1;
    int n = n0 + node;
    if (n >= cN) return;
    const float* a  = sA + isR * cF2 + h * 64;
    const float* fr = sF + node * 200 + h * 64;
    float acc = 0.f;
#pragma unroll
    for (int k = 0; k < 64; k++) acc += fr[k] * a[k];
    float* outp = isR ? g_er4 : g_el4;
    outp[(r * cN + n) * 4 + h] = acc;
}

// ------------------------- GAT gather: shift-free softmax + weighted agg + relu -------------------------
__global__ void __launch_bounds__(256) k_ggat(const float* __restrict__ bg) {
    int gw = blockIdx.x * 8 + (threadIdx.x >> 5);
    int lane = threadIdx.x & 31;
    if (gw >= cN) return;
    int n = gw;
    int p = lane * 2;
    float2 acc0, acc1, acc2;
    acc0.x = bg[p]          + bg[192 + p]          + bg[384 + p];
    acc0.y = bg[p + 1]      + bg[192 + p + 1]      + bg[384 + p + 1];
    acc1.x = bg[64 + p]     + bg[256 + p]          + bg[448 + p];
    acc1.y = bg[64 + p + 1] + bg[256 + p + 1]      + bg[448 + p + 1];
    acc2.x = bg[128 + p]    + bg[320 + p]          + bg[512 + p];
    acc2.y = bg[128 + p + 1]+ bg[320 + p + 1]      + bg[512 + p + 1];
#define GG_BODY(J) { \
    int s_ = __ldg(&g_esrc[J]); \
    size_t sb_ = (size_t)(r * cN + s_); \
    float4 el_ = __ldg((const float4*)g_el4 + sb_); \
    float e0_ = el_.x + er.x, e1_ = el_.y + er.y, e2_ = el_.z + er.z; \
    e0_ = e0_ > 0.f ? e0_ : 0.2f * e0_; \
    e1_ = e1_ > 0.f ? e1_ : 0.2f * e1_; \
    e2_ = e2_ > 0.f ? e2_ : 0.2f * e2_; \
    float w0_ = __expf(e0_), w1_ = __expf(e1_), w2_ = __expf(e2_); \
    const float2* fr_ = (const float2*)(g_f + sb_ * 192); \
    float2 f0_ = __ldg(fr_ + lane); \
    float2 f1_ = __ldg(fr_ + 32 + lane); \
    float2 f2_ = __ldg(fr_ + 64 + lane); \
    z0 += w0_; z1 += w1_; z2 += w2_; \
    t0.x += w0_ * f0_.x; t0.y += w0_ * f0_.y; \
    t1.x += w1_ * f1_.x; t1.y += w1_ * f1_.y; \
    t2.x += w2_ * f2_.x; t2.y += w2_ * f2_.y; }
#pragma unroll
    for (int r = 0; r < 3; r++) {
        int idx = r * cN + n;
        float4 er = __ldg((const float4*)g_er4 + idx);
        float z0 = 0.f, z1 = 0.f, z2 = 0.f;
        float2 t0 = {0.f, 0.f}, t1 = {0.f, 0.f}, t2 = {0.f, 0.f};
        int beg = g_off[idx], end = g_off[idx + 1];
        int j = beg;
        for (; j + 4 <= end; j += 4) { GG_BODY(j) GG_BODY(j + 1) GG_BODY(j + 2) GG_BODY(j + 3) }
        for (; j < end; ++j) { GG_BODY(j) }
        float r0 = 1.f / (z0 + 1e-9f), r1 = 1.f / (z1 + 1e-9f), r2 = 1.f / (z2 + 1e-9f);
        acc0.x += t0.x * r0; acc0.y += t0.y * r0;
        acc1.x += t1.x * r1; acc1.y += t1.y * r1;
        acc2.x += t2.x * r2; acc2.y += t2.y * r2;
    }
#undef GG_BODY
    float2* o0 = (float2*)(g_gat + (size_t)n * 192)       + lane;
    float2* o1 = (float2*)(g_gat + (size_t)n * 192 + 64)  + lane;
    float2* o2 = (float2*)(g_gat + (size_t)n * 192 + 128) + lane;
    o0->x = fmaxf(acc0.x, 0.f); o0->y = fmaxf(acc0.y, 0.f);
    o1->x = fmaxf(acc1.x, 0.f); o1->y = fmaxf(acc1.y, 0.f);
    o2->x = fmaxf(acc2.x, 0.f); o2->y = fmaxf(acc2.y, 0.f);
}

// ------------------------- conv2 matmul: gat @ W2[r], per head -------------------------
__global__ void k_mm2(const float* __restrict__ W2) {
    __shared__ float sX[32 * 64];
    int r = blockIdx.y, n0 = blockIdx.x * 32, tid = threadIdx.x;   // 128 threads
    for (int t = tid; t < 32 * 64; t += 128) {
        int row = t >> 6;
        sX[t] = (n0 + row < cM) ? g_gat[(size_t)n0 * 64 + t] : 0.f;
    }
    __syncthreads();
    int j = tid & 63, half = tid >> 6;
    const float* Wp = W2 + r * 64 * 64 + j;
    float acc[16];
#pragma unroll
    for (int m = 0; m < 16; m++) acc[m] = 0.f;
    for (int k = 0; k < 64; k++) {
        float w = Wp[k * 64];
#pragma unroll
        for (int m = 0; m < 16; m++)
            acc[m] += sX[((half << 4) + m) * 64 + k] * w;
    }
#pragma unroll
    for (int m = 0; m < 16; m++) {
        int n = n0 + (half << 4) + m;
        if (n < cM) g_xW2[((size_t)r * cM + n) * 64 + j] = acc[m];
    }
}

// ------------------------- conv2 gather + sigmoid (fused) -------------------------
__global__ void __launch_bounds__(256) k_gath2(const float* __restrict__ b2) {
    int gw = blockIdx.x * 8 + (threadIdx.x >> 5);
    int lane = threadIdx.x & 31;
    if (gw >= cN) return;
    int n = gw;
    int p = lane * 2;
    float bx = b2[p]     + b2[64 + p]     + b2[128 + p];
    float by = b2[p + 1] + b2[64 + p + 1] + b2[128 + p + 1];
    float2 acc0 = {bx, by}, acc1 = {bx, by}, acc2 = {bx, by};
#define G2_BODY(J) { \
    int s_ = __ldg(&g_esrc[J]); \
    float sc_ = __ldg(&g_ns[r * cN + s_]) * nd; \
    const float2* base_ = (const float2*)(g_xW2 + ((size_t)r * cM + (size_t)s_ * 3) * 64); \
    float2 f0_ = __ldg(base_ + lane); \
    float2 f1_ = __ldg(base_ + 32 + lane); \
    float2 f2_ = __ldg(base_ + 64 + lane); \
    acc0.x += sc_ * f0_.x; acc0.y += sc_ * f0_.y; \
    acc1.x += sc_ * f1_.x; acc1.y += sc_ * f1_.y; \
    acc2.x += sc_ * f2_.x; acc2.y += sc_ * f2_.y; }
#pragma unroll
    for (int r = 0; r < 3; r++) {
        int idx = r * cN + n;
        float nd = g_nd[idx];
        int beg = g_off[idx], end = g_off[idx + 1];
        int j = beg;
        for (; j + 4 <= end; j += 4) { G2_BODY(j) G2_BODY(j + 1) G2_BODY(j + 2) G2_BODY(j + 3) }
        for (; j < end; ++j) { G2_BODY(j) }
    }
#undef G2_BODY
    float2* o0 = (float2*)(g_acc2 + (size_t)n * 192)       + lane;
    float2* o1 = (float2*)(g_acc2 + (size_t)n * 192 + 64)  + lane;
    float2* o2 = (float2*)(g_acc2 + (size_t)n * 192 + 128) + lane;
    o0->x = sigmoidf_(acc0.x); o0->y = sigmoidf_(acc0.y);
    o1->x = sigmoidf_(acc1.x); o1->y = sigmoidf_(acc1.y);
    o2->x = sigmoidf_(acc2.x); o2->y = sigmoidf_(acc2.y);
}

// ------------------------- node counts per graph -------------------------
__global__ void k_cnt(const int* __restrict__ gid) {
    int i = blockIdx.x * blockDim.x + threadIdx.x;
    if (i >= cN) return;
    int g = gid[i];
    unsigned m = __match_any_sync(__activemask(), g);
    int leader = __ffs(m) - 1;
    if ((threadIdx.x & 31) == leader)
        atomicAdd(&g_cnt[g], (float)__popc(m));
}

// ------------------------- graph pooling (acc2 already sigmoid'd) -------------------------
__global__ void k_pool(const int* __restrict__ gid) {
    int n0 = blockIdx.x * 64;
    int j  = threadIdx.x;                        // 192 threads
    int curg = -1;
    float a = 0.f;
#pragma unroll 1
    for (int m = 0; m < 64; m++) {
        int n = n0 + m;
        if (n >= cN) break;
        int g = __ldg(&gid[n]);
        float v = g_acc2[(size_t)n * 192 + j];
        if (g != curg) {
            if (curg >= 0) atomicAdd(&g_pool[curg * 192 + j], a);
            curg = g; a = 0.f;
        }
        a += v;
    }
    if (curg >= 0) atomicAdd(&g_pool[curg * 192 + j], a);
}

// ------------------------- final classifier + mean -------------------------
__global__ void k_final(const float* __restrict__ Wc, const float* __restrict__ bc,
                        float* __restrict__ out) {
    int t = threadIdx.x;                          // 384 threads
    int b = t / 48, rem = t % 48, h = rem / 16, c = rem & 15;
    float inv = 1.f / fmaxf(g_cnt[b], 1.f);
    const float* P = g_pool + (b * 3 + h) * 64;
    float dot = bc[c];
#pragma unroll
    for (int k = 0; k < 64; k++) dot += P[k] * inv * Wc[k * 16 + c];
    float sg = 1.f / (1.f + expf(-dot));
#pragma unroll
    for (int off = 8; off; off >>= 1) sg += __shfl_xor_sync(0xffffffffu, sg, off);
    if (c == 0) out[b * 3 + h] = sg * (1.f / 16.f);
}

// ------------------------- launcher -------------------------
extern "C" void kernel_launch(void* const* d_in, const int* in_sizes, int n_in,
                              void* d_out, int out_size) {
    const float* x   = (const float*)d_in[0];
    const int*   src = (const int*)  d_in[1];
    const int*   dst = (const int*)  d_in[2];
    const int*   gid = (const int*)  d_in[3];
    const float* W1  = (const float*)d_in[4];
    const float* b1  = (const float*)d_in[5];
    const float* Wg  = (const float*)d_in[6];
    const float* al  = (const float*)d_in[7];
    const float* ar  = (const float*)d_in[8];
    const float* bg  = (const float*)d_in[9];
    const float* W2  = (const float*)d_in[10];
    const float* b2  = (const float*)d_in[11];
    const float* Wc  = (const float*)d_in[12];
    const float* bc  = (const float*)d_in[13];
    float* out = (float*)d_out;

    // CSR build
    k_init0<<<(cRN + 255) / 256, 256>>>();
    k_deg<<<(cRE + 255) / 256, 256>>>(src, dst);
    k_norm<<<(cRN + 255) / 256, 256>>>();
    k_scanA<<<SCAN_NB, 256>>>();
    k_scanB<<<1, 256>>>();
    k_scanC<<<(cRN + 255) / 256, 256>>>();
    k_fill<<<(cRE + 255) / 256, 256>>>(src, dst);

    // layer 1
    dim3 g1((cN + 31) / 32, cR);
    k_mm1<<<g1, 128>>>(x, W1);
    k_gath1<<<(cN + 7) / 8, 256>>>(b1);

    // GAT
    dim3 gF((cN + 15) / 16, cR);
    k_mmF<<<gF, 192>>>(Wg);
    dim3 gE((cN + 31) / 32, cR);
    k_eler<<<gE, 192>>>(al, ar);
    k_ggat<<<(cN + 7) / 8, 256>>>(bg);

    // layer 2
    dim3 g2((cM + 31) / 32, cR);
    k_mm2<<<g2, 128>>>(W2);
    k_gath2<<<(cN + 7) / 8, 256>>>(b2);

    // pooling + classifier
    k_cnt<<<(cN + 255) / 256, 256>>>(gid);
    k_pool<<<(cN + 63) / 64, 192>>>(gid);
    k_final<<<1, 384>>>(Wc, bc, out);
}